// round 6
// baseline (speedup 1.0000x reference)
#include <cuda_runtime.h>
#include <cuda_bf16.h>

#define BATCH 32
#define SEQ   4096
#define EMBED 512
#define HID   256
#define OUTD  128
#define DECAYF 0.95f
#define LOG2_INV_D 0.07400058144377693f   // log2(1/0.95)

__device__ float    g_xm[SEQ * EMBED];    // batch-mean [4096][512]
__device__ float    g_curT[HID * SEQ];    // currents TRANSPOSED [256][4096]
__device__ float    g_cnt[HID];           // spike counts
__device__ unsigned g_done;               // last-block flag (self-resetting)

// ---------------------------------------------------------------------------
// Kernel 1: batch mean over B=32 (82% of HBM — keep).
// ---------------------------------------------------------------------------
__global__ void snn_mean_kernel(const float* __restrict__ x) {
    const int NF4 = (SEQ * EMBED) / 4;
    int i = blockIdx.x * blockDim.x + threadIdx.x;
    if (i >= NF4) return;
    const float4* x4 = reinterpret_cast<const float4*>(x);
    float sx = 0.f, sy = 0.f, sz = 0.f, sw = 0.f;
#pragma unroll
    for (int b = 0; b < BATCH; b++) {
        float4 v = x4[(size_t)b * NF4 + i];
        sx += v.x; sy += v.y; sz += v.z; sw += v.w;
    }
    const float inv = 1.0f / 32.0f;
    float4 r; r.x = sx * inv; r.y = sy * inv; r.z = sz * inv; r.w = sw * inv;
    reinterpret_cast<float4*>(g_xm)[i] = r;
}

// ---------------------------------------------------------------------------
// Kernel 2: SGEMM currents^T = (xm @ W1)^T.
// 64(s) x 128(h) tile, 256 threads (2 warps/SMSP), micro 4s x 8h,
// n-packed f32x2, cp.async double-buffered. Grid (2, 64) = 128 blocks.
// ---------------------------------------------------------------------------
#define GBM 64
#define GBN 128
#define GBK 32
#define APITCH 36
#define SA_SZ (GBM * APITCH)      // 2304 floats
#define SB_SZ (GBK * GBN)         // 4096 floats
// layout: sA0 @0, sA1 @2304, sB0 @4608, sB1 @8704; total 12800 floats
#define GEMM_SMEM_BYTES (12800 * 4)

typedef unsigned long long ull;

__device__ __forceinline__ void fma2(ull& d, ull a, ull b) {
    asm("fma.rn.f32x2 %0, %1, %2, %0;" : "+l"(d) : "l"(a), "l"(b));
}
__device__ __forceinline__ ull dup2(float a) {
    ull r;
    asm("mov.b64 %0, {%1, %1};" : "=l"(r) : "f"(a));
    return r;
}
__device__ __forceinline__ void cp16(unsigned dst, const void* src) {
    asm volatile("cp.async.cg.shared.global [%0], [%1], 16;" :: "r"(dst), "l"(src));
}
__device__ __forceinline__ void cp_commit() {
    asm volatile("cp.async.commit_group;");
}
__device__ __forceinline__ void cp_wait0() {
    asm volatile("cp.async.wait_group 0;");
}

__global__ void __launch_bounds__(256, 1)
snn_gemm_kernel(const float* __restrict__ W1) {
    extern __shared__ float gsm[];
    const unsigned smem_u32 = (unsigned)__cvta_generic_to_shared(gsm);

    const int tid = threadIdx.x;
    const int h0  = blockIdx.x * GBN;
    const int s0  = blockIdx.y * GBM;
    const int mgrp = tid >> 4;       // 0..15 -> 4 s-rows each
    const int ngrp = tid & 15;       // 0..15 -> 8 h-cols each
    const int m0 = mgrp * 4;
    const int n0 = ngrp * 8;

    auto load_chunk = [&](int c, int buf) {
        const int k0 = c * GBK;
        unsigned dA = smem_u32 + (buf * SA_SZ) * 4;
#pragma unroll
        for (int l = 0; l < 2; l++) {
            int f   = tid + l * 256;      // 0..511
            int row = f >> 3;
            int seg = f & 7;
            cp16(dA + (row * APITCH + seg * 4) * 4,
                 &g_xm[(size_t)(s0 + row) * EMBED + k0 + seg * 4]);
        }
        unsigned dB = smem_u32 + (4608 + buf * SB_SZ) * 4;
#pragma unroll
        for (int l = 0; l < 4; l++) {
            int f   = tid + l * 256;      // 0..1023
            int row = f >> 5;
            int seg = f & 31;
            cp16(dB + (row * GBN + seg * 4) * 4,
                 &W1[(size_t)(k0 + row) * HID + h0 + seg * 4]);
        }
        cp_commit();
    };

    ull acc[4][4];
#pragma unroll
    for (int j = 0; j < 4; j++)
#pragma unroll
        for (int p = 0; p < 4; p++) acc[j][p] = 0ull;

    load_chunk(0, 0);

    const int NCHUNK = EMBED / GBK;   // 16
#pragma unroll 1
    for (int c = 0; c < NCHUNK; c++) {
        cp_wait0();
        __syncthreads();
        if (c + 1 < NCHUNK) load_chunk(c + 1, (c + 1) & 1);

        const float* pA = gsm + (c & 1) * SA_SZ + m0 * APITCH;
        const float* pB = gsm + 4608 + (c & 1) * SB_SZ + n0;
#pragma unroll 4
        for (int k = 0; k < GBK; k++) {
            ulonglong2 b01 = *reinterpret_cast<const ulonglong2*>(pB + k * GBN);
            ulonglong2 b23 = *reinterpret_cast<const ulonglong2*>(pB + k * GBN + 4);
#pragma unroll
            for (int j = 0; j < 4; j++) {
                ull ad = dup2(pA[j * APITCH + k]);
                fma2(acc[j][0], ad, b01.x);
                fma2(acc[j][1], ad, b01.y);
                fma2(acc[j][2], ad, b23.x);
                fma2(acc[j][3], ad, b23.y);
            }
        }
        __syncthreads();
    }

    // epilogue: stage transposed [h][s] tile, coalesced f4 stores
    float* sT = gsm;                  // [128][68] = 8704 floats
#pragma unroll
    for (int j = 0; j < 4; j++) {
#pragma unroll
        for (int p = 0; p < 4; p++) {
            float2 v = *reinterpret_cast<float2*>(&acc[j][p]);
            sT[(n0 + 2 * p + 0) * 68 + (m0 + j)] = v.x;
            sT[(n0 + 2 * p + 1) * 68 + (m0 + j)] = v.y;
        }
    }
    __syncthreads();
#pragma unroll
    for (int l = 0; l < 8; l++) {
        int f    = tid + l * 256;     // 0..2047
        int hrow = f >> 4;
        int seg  = f & 15;
        float4 v = *reinterpret_cast<float4*>(&sT[hrow * 68 + seg * 4]);
        *reinterpret_cast<float4*>(
            &g_curT[(size_t)(h0 + hrow) * SEQ + s0 + seg * 4]) = v;
    }
}

// ---------------------------------------------------------------------------
// Kernel 3: warp-window LIF scan, TWO units interleaved per warp, + fused
// output projection. 32 blocks x 128 threads; warp w handles units
// h = 8*blockIdx + 2w, +1. Same validated per-window algebra as R5:
// P_t = prefix(c_i d^{-i}); spike <=> Q_t = P_t - d^{-t} >= X.
// ---------------------------------------------------------------------------
__global__ void __launch_bounds__(128, 1)
snn_table_out_kernel(const float* __restrict__ W2, float* __restrict__ out) {
    extern __shared__ float scs[];    // 8 rows x 4096 floats = 128 KB
    __shared__ unsigned slast;

    const int tid  = threadIdx.x;
    const int lane = tid & 31;
    const int w    = tid >> 5;
    const int hbase = blockIdx.x * 8;

    // stage 8 contiguous unit rows (coalesced float4)
    const float4* src = reinterpret_cast<const float4*>(&g_curT[(size_t)hbase * SEQ]);
#pragma unroll
    for (int l = 0; l < 64; l++)
        reinterpret_cast<float4*>(scs)[tid + l * 128] = src[tid + l * 128];
    __syncthreads();

    const float dinv = exp2f((float)lane * LOG2_INV_D);   // d^{-lane}
    const float d31  = exp2f(-31.0f * LOG2_INV_D);        // d^31

    const float* row0 = &scs[(2 * w + 0) * SEQ];
    const float* row1 = &scs[(2 * w + 1) * SEQ];

    float X[2]  = {0.f, 0.f};
    int   o[2]  = {0, 0};
    int   cb[2] = {0, 0};     // carry flag
    int   co[2] = {0, 0};     // carry offset
    int   cnt[2] = {0, 0};

#pragma unroll 1
    for (int win = 0; win < SEQ / 32; win++) {
        // two independent prefix scans (interleaved shfl chains)
        float p0 = row0[win * 32 + lane] * dinv;
        float p1 = row1[win * 32 + lane] * dinv;
#pragma unroll
        for (int off = 1; off < 32; off <<= 1) {
            float v0 = __shfl_up_sync(0xffffffffu, p0, off);
            float v1 = __shfl_up_sync(0xffffffffu, p1, off);
            if (lane >= off) { p0 += v0; p1 += v1; }
        }
        const float Q0 = p0 - dinv, Q1 = p1 - dinv;
        const float P31_0 = __shfl_sync(0xffffffffu, p0, 31);
        const float P31_1 = __shfl_sync(0xffffffffu, p1, 31);

        if (cb[0]) {
            o[0] = co[0];
            X[0] = (co[0] == 0) ? 0.f : __shfl_sync(0xffffffffu, p0, co[0] - 1);
            cb[0] = 0;
        }
        if (cb[1]) {
            o[1] = co[1];
            X[1] = (co[1] == 0) ? 0.f : __shfl_sync(0xffffffffu, p1, co[1] - 1);
            cb[1] = 0;
        }

        // interleaved spike chains (warp-uniform control)
        int act0 = 1, act1 = 1;
        while (act0 | act1) {
            unsigned m0 = 0, m1 = 0;
            if (act0) m0 = __ballot_sync(0xffffffffu, (Q0 >= X[0]) && (lane >= o[0]));
            else      __syncwarp();
            if (act1) m1 = __ballot_sync(0xffffffffu, (Q1 >= X[1]) && (lane >= o[1]));
            else      __syncwarp();

            if (act0) {
                if (!m0) {
                    float m31 = d31 * (P31_0 - X[0]);
                    X[0] = -DECAYF * m31; o[0] = 0; act0 = 0;
                } else {
                    int ts = __ffs(m0) - 1;
                    cnt[0]++;
                    if (ts >= 29) { cb[0] = 1; co[0] = ts - 29; act0 = 0; }
                    else { o[0] = ts + 3; X[0] = __shfl_sync(0xffffffffu, p0, ts + 2); }
                }
            }
            if (act1) {
                if (!m1) {
                    float m31 = d31 * (P31_1 - X[1]);
                    X[1] = -DECAYF * m31; o[1] = 0; act1 = 0;
                } else {
                    int ts = __ffs(m1) - 1;
                    cnt[1]++;
                    if (ts >= 29) { cb[1] = 1; co[1] = ts - 29; act1 = 0; }
                    else { o[1] = ts + 3; X[1] = __shfl_sync(0xffffffffu, p1, ts + 2); }
                }
            }
        }
    }

    if (lane == 0) {
        g_cnt[hbase + 2 * w + 0] = (float)cnt[0];
        g_cnt[hbase + 2 * w + 1] = (float)cnt[1];
    }
    __syncthreads();
    __threadfence();
    if (tid == 0) slast = atomicAdd(&g_done, 1u);
    __syncthreads();

    if (slast == 31) {                         // last of 32 blocks
        __threadfence();
        volatile float* vc = g_cnt;
        float a = 0.f;
#pragma unroll 16
        for (int k = 0; k < HID; k++)
            a += vc[k] * W2[(size_t)k * OUTD + tid];
        a *= (1.0f / (float)SEQ);
#pragma unroll
        for (int b = 0; b < BATCH; b++)
            out[(size_t)b * OUTD + tid] = a;
        __threadfence();
        if (tid == 0) g_done = 0;              // reset for next replay
    }
}

// ---------------------------------------------------------------------------
extern "C" void kernel_launch(void* const* d_in, const int* in_sizes, int n_in,
                              void* d_out, int out_size) {
    const float* x  = (const float*)d_in[0];   // [32][4096][512]
    const float* w1 = (const float*)d_in[1];   // [512][256]
    const float* w2 = (const float*)d_in[2];   // [256][128]
    float* out = (float*)d_out;                // [32][128]

    cudaFuncSetAttribute(snn_gemm_kernel,
                         cudaFuncAttributeMaxDynamicSharedMemorySize,
                         GEMM_SMEM_BYTES);
    cudaFuncSetAttribute(snn_table_out_kernel,
                         cudaFuncAttributeMaxDynamicSharedMemorySize,
                         8 * SEQ * (int)sizeof(float));

    snn_mean_kernel<<<(SEQ * EMBED / 4 + 255) / 256, 256>>>(x);
    snn_gemm_kernel<<<dim3(HID / GBN, SEQ / GBM), 256, GEMM_SMEM_BYTES>>>(w1);
    snn_table_out_kernel<<<HID / 8, 128, 8 * SEQ * sizeof(float)>>>(w2, out);
}